// round 15
// baseline (speedup 1.0000x reference)
#include <cuda_runtime.h>
#include <math.h>

#define NM 1024
#define HH 256
#define WW 256
#define HW 65536
#define OUT_MASKS ((size_t)NM * HW)            // 67108864 floats
#define OUT_KEEP_OFF OUT_MASKS                 // keep[1024]
#define OUT_BOX_OFF (OUT_MASKS + NM)           // boxes[1024*4]

#define IOU_THRESH 0.88f

// ---- scratch (no allocations allowed) ----
__device__ int   g_hi[NM];
__device__ int   g_lo[NM];
__device__ int   g_minr[NM];
__device__ int   g_maxr[NM];
__device__ int   g_minc[NM];
__device__ int   g_maxc[NM];
__device__ float g_gated[NM];
__device__ int   g_npass;              // # iou-pass masks (overwritten each launch)
__device__ int   g_plist[NM];          // compact list of iou-pass masks

// ============================================================
// Kernel A — EXACT R11 version (measured 84.6-95.9us, regs=32,
// occ~91%). Untouchable.
// ============================================================
__global__ void __launch_bounds__(256) sam_fused_kernel(const float* __restrict__ logits,
                                                        const float* __restrict__ iou_preds,
                                                        float* __restrict__ out)
{
    const int tid = threadIdx.x;

    if (blockIdx.x >= NM) {
        // ---- zero-fill path ----
        const int b = blockIdx.x - NM;
        const int n = b >> 2;
        const int q = b & 3;
        if (iou_preds[n] > IOU_THRESH) return;   // handled by out kernel
        float4* __restrict__ o4 = reinterpret_cast<float4*>(out)
                                + (size_t)n * (HW / 4) + (size_t)q * (HW / 16);
        const float4 z = make_float4(0.0f, 0.0f, 0.0f, 0.0f);
#pragma unroll
        for (int it = 0; it < 16; ++it)
            __stcs(&o4[it * 256 + tid], z);
        return;
    }

    // ---- stats path ----
    const int n = blockIdx.x;
    const float4* __restrict__ p =
        reinterpret_cast<const float4*>(logits + (size_t)n * HW);

    int hi = 0, lo = 0;
    int minr = HH, maxr = -1, minc = WW, maxc = -1;

#pragma unroll 8
    for (int it = 0; it < 64; ++it) {
        const int i4 = it * 256 + tid;
        const float4 v = __ldcs(&p[i4]);
        const int e   = i4 << 2;
        const int row = e >> 8;
        const int col = e & 255;

        const float vs0 = v.x, vs1 = v.y, vs2 = v.z, vs3 = v.w;
        hi += (vs0 > 1.0f) + (vs1 > 1.0f) + (vs2 > 1.0f) + (vs3 > 1.0f);
        lo += (vs0 > -1.0f) + (vs1 > -1.0f) + (vs2 > -1.0f) + (vs3 > -1.0f);

        const bool b0 = vs0 > 0.0f, b1 = vs1 > 0.0f, b2 = vs2 > 0.0f, b3 = vs3 > 0.0f;
        if (b0 | b1 | b2 | b3) {
            minr = min(minr, row);
            maxr = max(maxr, row);
            if (b0) { minc = min(minc, col);     maxc = max(maxc, col);     }
            if (b1) { minc = min(minc, col + 1); maxc = max(maxc, col + 1); }
            if (b2) { minc = min(minc, col + 2); maxc = max(maxc, col + 2); }
            if (b3) { minc = min(minc, col + 3); maxc = max(maxc, col + 3); }
        }
    }

#pragma unroll
    for (int o = 16; o > 0; o >>= 1) {
        hi   += __shfl_down_sync(0xFFFFFFFFu, hi, o);
        lo   += __shfl_down_sync(0xFFFFFFFFu, lo, o);
        minr = min(minr, __shfl_down_sync(0xFFFFFFFFu, minr, o));
        maxr = max(maxr, __shfl_down_sync(0xFFFFFFFFu, maxr, o));
        minc = min(minc, __shfl_down_sync(0xFFFFFFFFu, minc, o));
        maxc = max(maxc, __shfl_down_sync(0xFFFFFFFFu, maxc, o));
    }

    __shared__ int s_hi[8], s_lo[8], s_minr[8], s_maxr[8], s_minc[8], s_maxc[8];
    const int w = tid >> 5;
    if ((tid & 31) == 0) {
        s_hi[w] = hi; s_lo[w] = lo;
        s_minr[w] = minr; s_maxr[w] = maxr;
        s_minc[w] = minc; s_maxc[w] = maxc;
    }
    __syncthreads();
    if (tid == 0) {
#pragma unroll
        for (int k = 1; k < 8; ++k) {
            hi += s_hi[k]; lo += s_lo[k];
            minr = min(minr, s_minr[k]); maxr = max(maxr, s_maxr[k]);
            minc = min(minc, s_minc[k]); maxc = max(maxc, s_maxc[k]);
        }
        g_hi[n] = hi;   g_lo[n] = lo;
        g_minr[n] = minr; g_maxr[n] = maxr;
        g_minc[n] = minc; g_maxc[n] = maxc;
    }
}

// ============================================================
// Kernel N: 1 block, 256 threads. Boxes, plist, compaction,
// rank over nvalid, predicated warp NMS, keep + g_gated.
// ============================================================
__global__ void __launch_bounds__(256) sam_nms_kernel(const float* __restrict__ iou_preds,
                                                      float* __restrict__ out)
{
    const int tid = threadIdx.x;

    __shared__ float s_key[NM];
    __shared__ int   s_idx[NM];
    __shared__ float s_sl[NM], s_st[NM], s_sr[NM], s_sb[NM];
    __shared__ float s_sa[NM];
    __shared__ int   s_sidx[NM];
    __shared__ float s_sscore[NM];
    __shared__ unsigned char s_keep[NM];
    __shared__ int   s_nv, s_np;

    if (tid == 0) { s_nv = 0; s_np = 0; }
    __syncthreads();

    float my_sc[4], my_bl[4], my_bt[4], my_br[4], my_bb[4];
    int   my_m[4];
    bool  my_valid[4];
#pragma unroll
    for (int k = 0; k < 4; ++k) {
        const int m = tid + k * 256;
        my_m[k] = m;
        const float sc = iou_preds[m];
        const float fhi = (float)g_hi[m];
        const float flo = (float)g_lo[m];
        const float stability = fhi / fmaxf(flo, 1.0f);
        const int mr0 = g_minr[m], mr1 = g_maxr[m];
        const int mc0 = g_minc[m], mc1 = g_maxc[m];
        const bool empty = (mr1 < 0);
        my_sc[k] = sc;
        my_bl[k] = empty ? 0.0f : (float)mc0;
        my_bt[k] = empty ? 0.0f : (float)mr0;
        my_br[k] = empty ? 0.0f : (float)mc1;
        my_bb[k] = empty ? 0.0f : (float)mr1;
        my_valid[k] = (sc > IOU_THRESH) && (stability >= 0.95f);

        float* ob = out + OUT_BOX_OFF + (size_t)m * 4;
        ob[0] = my_bl[k]; ob[1] = my_bt[k]; ob[2] = my_br[k]; ob[3] = my_bb[k];

        if (sc > IOU_THRESH) {
            const int pp = atomicAdd(&s_np, 1);
            g_plist[pp] = m;
        }
        if (my_valid[k]) {
            const int pos = atomicAdd(&s_nv, 1);
            s_key[pos] = sc;
            s_idx[pos] = m;
        }
    }
    __syncthreads();
    const int nvalid = s_nv;
    if (tid == 0) g_npass = s_np;

    // canonical stable rank (score desc, orig idx asc) + scatter
#pragma unroll
    for (int k = 0; k < 4; ++k) {
        if (!my_valid[k]) continue;
        const float sc = my_sc[k];
        const int   m  = my_m[k];
        int rank = 0;
        for (int i = 0; i < nvalid; ++i) {
            const float kk = s_key[i];
            rank += (kk > sc) || ((kk == sc) && (s_idx[i] < m));
        }
        s_sl[rank] = my_bl[k]; s_st[rank] = my_bt[k];
        s_sr[rank] = my_br[k]; s_sb[rank] = my_bb[k];
        s_sa[rank] = fmaxf(my_br[k] - my_bl[k], 0.0f) * fmaxf(my_bb[k] - my_bt[k], 0.0f);
        s_sidx[rank] = m; s_sscore[rank] = sc;
    }
    __syncthreads();

    // warp 0: predicated greedy NMS (uniform inner trip count)
    if (tid < 32) {
        const int lane = tid;
        const int nslot = (nvalid + 31) >> 5;
        unsigned alive = 0;
        for (int t = 0; t < nslot; ++t)
            if (lane + (t << 5) < nvalid) alive |= (1u << t);

        for (int i = 0; i < nvalid; ++i) {
            const unsigned oa = __shfl_sync(0xFFFFFFFFu, alive, i & 31);
            if ((oa >> (i >> 5)) & 1) {                 // warp-uniform test
                const float il = s_sl[i], it_ = s_st[i];
                const float ir = s_sr[i], ib = s_sb[i];
                const float areaI = s_sa[i];
                for (int t = 0; t < nslot; ++t) {
                    const int j = lane + (t << 5);
                    const bool act = (j > i) && (j < nvalid) && ((alive >> t) & 1);
                    const float tl = s_sl[j], tt = s_st[j];
                    const float tr = s_sr[j], tb = s_sb[j];
                    const float x0 = fmaxf(il, tl), y0 = fmaxf(it_, tt);
                    const float x1 = fminf(ir, tr), y1 = fminf(ib, tb);
                    const float inter = fmaxf(x1 - x0, 0.0f) * fmaxf(y1 - y0, 0.0f);
                    const float uni = fmaxf(areaI + s_sa[j] - inter, 1e-6f);
                    if (act && (inter / uni > 0.7f)) alive &= ~(1u << t);
                }
            }
        }
        for (int t = 0; t < nslot; ++t) {
            const int j = lane + (t << 5);
            if (j < nvalid) s_keep[j] = (alive >> t) & 1;
        }
    }
    __syncthreads();

    // defaults, then kept overrides
#pragma unroll
    for (int k = 0; k < 4; ++k) {
        const int m = tid + k * 256;
        g_gated[m] = 0.0f;
        out[OUT_KEEP_OFF + m] = 0.0f;
    }
    __syncthreads();
    for (int s = tid; s < nvalid; s += 256) {
        if (s_keep[s]) {
            const int m = s_sidx[s];
            g_gated[m] = s_sscore[s];
            out[OUT_KEEP_OFF + m] = 1.0f;
        }
    }
}

// ============================================================
// Kernel O: latency-optimized output for iou-pass masks.
// 8 tiles per mask (8KB) -> ~8*npass active blocks; batched
// loads (all 8 float4 in flight before compute) for MLP=8.
// ============================================================
__global__ void __launch_bounds__(256) sam_out_kernel(const float* __restrict__ logits,
                                                      float* __restrict__ out)
{
    const int tid = threadIdx.x;
    const int tiles = 8 * g_npass;            // 2048 float4 per tile
    const float4 z = make_float4(0.0f, 0.0f, 0.0f, 0.0f);

    for (int t = blockIdx.x; t < tiles; t += gridDim.x) {
        const int n = g_plist[t >> 3];
        const int q = t & 7;
        const float g = g_gated[n];
        const size_t base4 = (size_t)n * (HW / 4) + (size_t)q * (HW / 32);
        float4* __restrict__ o4 = reinterpret_cast<float4*>(out) + base4;

        if (g == 0.0f) {
#pragma unroll
            for (int it = 0; it < 8; ++it)
                __stcs(&o4[it * 256 + tid], z);
        } else {
            const float4* __restrict__ in4 =
                reinterpret_cast<const float4*>(logits) + base4;
            float4 v[8];
#pragma unroll
            for (int it = 0; it < 8; ++it)     // 8 loads in flight
                v[it] = __ldcs(&in4[it * 256 + tid]);
#pragma unroll
            for (int it = 0; it < 8; ++it) {
                float4 r;
                r.x = g / (1.0f + __expf(-v[it].x));
                r.y = g / (1.0f + __expf(-v[it].y));
                r.z = g / (1.0f + __expf(-v[it].z));
                r.w = g / (1.0f + __expf(-v[it].w));
                __stcs(&o4[it * 256 + tid], r);
            }
        }
    }
}

extern "C" void kernel_launch(void* const* d_in, const int* in_sizes, int n_in,
                              void* d_out, int out_size)
{
    const float* logits    = (const float*)d_in[0];  // [1024,256,256]
    const float* iou_preds = (const float*)d_in[1];  // [1024]
    float* out = (float*)d_out;

    sam_fused_kernel<<<NM + NM * 4, 256>>>(logits, iou_preds, out);
    sam_nms_kernel<<<1, 256>>>(iou_preds, out);
    sam_out_kernel<<<1024, 256>>>(logits, out);
}

// round 16
// speedup vs baseline: 1.0302x; 1.0302x over previous
#include <cuda_runtime.h>
#include <math.h>

#define NM 1024
#define HH 256
#define WW 256
#define HW 65536
#define OUT_MASKS ((size_t)NM * HW)            // 67108864 floats
#define OUT_KEEP_OFF OUT_MASKS                 // keep[1024]
#define OUT_BOX_OFF (OUT_MASKS + NM)           // boxes[1024*4]

#define IOU_THRESH 0.88f

// ---- scratch (no allocations allowed) ----
__device__ int   g_hi[NM];
__device__ int   g_lo[NM];
__device__ int   g_minr[NM];
__device__ int   g_maxr[NM];
__device__ int   g_minc[NM];
__device__ int   g_maxc[NM];
__device__ float g_gated[NM];

// ============================================================
// Kernel A — EXACT R4/R11 version (measured 84.6-87.9us @73%
// DRAM, regs=32, occ=90%). Untouchable.
// ============================================================
__global__ void __launch_bounds__(256) sam_fused_kernel(const float* __restrict__ logits,
                                                        const float* __restrict__ iou_preds,
                                                        float* __restrict__ out)
{
    const int tid = threadIdx.x;

    if (blockIdx.x >= NM) {
        // ---- zero-fill path ----
        const int b = blockIdx.x - NM;
        const int n = b >> 2;
        const int q = b & 3;
        if (iou_preds[n] > IOU_THRESH) return;   // handled by out kernel
        float4* __restrict__ o4 = reinterpret_cast<float4*>(out)
                                + (size_t)n * (HW / 4) + (size_t)q * (HW / 16);
        const float4 z = make_float4(0.0f, 0.0f, 0.0f, 0.0f);
#pragma unroll
        for (int it = 0; it < 16; ++it)
            __stcs(&o4[it * 256 + tid], z);
        return;
    }

    // ---- stats path ----
    const int n = blockIdx.x;
    const float4* __restrict__ p =
        reinterpret_cast<const float4*>(logits + (size_t)n * HW);

    int hi = 0, lo = 0;
    int minr = HH, maxr = -1, minc = WW, maxc = -1;

#pragma unroll 8
    for (int it = 0; it < 64; ++it) {
        const int i4 = it * 256 + tid;
        const float4 v = __ldcs(&p[i4]);
        const int e   = i4 << 2;
        const int row = e >> 8;
        const int col = e & 255;

        const float vs0 = v.x, vs1 = v.y, vs2 = v.z, vs3 = v.w;
        hi += (vs0 > 1.0f) + (vs1 > 1.0f) + (vs2 > 1.0f) + (vs3 > 1.0f);
        lo += (vs0 > -1.0f) + (vs1 > -1.0f) + (vs2 > -1.0f) + (vs3 > -1.0f);

        const bool b0 = vs0 > 0.0f, b1 = vs1 > 0.0f, b2 = vs2 > 0.0f, b3 = vs3 > 0.0f;
        if (b0 | b1 | b2 | b3) {
            minr = min(minr, row);
            maxr = max(maxr, row);
            if (b0) { minc = min(minc, col);     maxc = max(maxc, col);     }
            if (b1) { minc = min(minc, col + 1); maxc = max(maxc, col + 1); }
            if (b2) { minc = min(minc, col + 2); maxc = max(maxc, col + 2); }
            if (b3) { minc = min(minc, col + 3); maxc = max(maxc, col + 3); }
        }
    }

#pragma unroll
    for (int o = 16; o > 0; o >>= 1) {
        hi   += __shfl_down_sync(0xFFFFFFFFu, hi, o);
        lo   += __shfl_down_sync(0xFFFFFFFFu, lo, o);
        minr = min(minr, __shfl_down_sync(0xFFFFFFFFu, minr, o));
        maxr = max(maxr, __shfl_down_sync(0xFFFFFFFFu, maxr, o));
        minc = min(minc, __shfl_down_sync(0xFFFFFFFFu, minc, o));
        maxc = max(maxc, __shfl_down_sync(0xFFFFFFFFu, maxc, o));
    }

    __shared__ int s_hi[8], s_lo[8], s_minr[8], s_maxr[8], s_minc[8], s_maxc[8];
    const int w = tid >> 5;
    if ((tid & 31) == 0) {
        s_hi[w] = hi; s_lo[w] = lo;
        s_minr[w] = minr; s_maxr[w] = maxr;
        s_minc[w] = minc; s_maxc[w] = maxc;
    }
    __syncthreads();
    if (tid == 0) {
#pragma unroll
        for (int k = 1; k < 8; ++k) {
            hi += s_hi[k]; lo += s_lo[k];
            minr = min(minr, s_minr[k]); maxr = max(maxr, s_maxr[k]);
            minc = min(minc, s_minc[k]); maxc = max(maxc, s_maxc[k]);
        }
        g_hi[n] = hi;   g_lo[n] = lo;
        g_minr[n] = minr; g_maxr[n] = maxr;
        g_minc[n] = minc; g_maxc[n] = maxc;
    }
}

// ============================================================
// Kernel N — R4's NMS kernel (1024 threads, ballot compaction,
// rank over nvalid) with ONE change: the block-barriered greedy
// loop is replaced by the predicated warp-synchronous NMS.
// ============================================================
__global__ void __launch_bounds__(1024) sam_nms_kernel(const float* __restrict__ iou_preds,
                                                       float* __restrict__ out)
{
    const int j = threadIdx.x;
    const int wid = j >> 5;
    const unsigned lane_lt = (1u << (j & 31)) - 1u;

    __shared__ int   s_wcnt[32];
    __shared__ float s_ckey[NM];     // compact keys (scores of valid)
    __shared__ int   s_cidx[NM];     // compact original indices
    __shared__ float s_sl[NM], s_st[NM], s_sr[NM], s_sb[NM];  // sorted boxes
    __shared__ float s_sa[NM];       // sorted areas
    __shared__ unsigned char s_keep[NM];

    const float score = iou_preds[j];
    const float hi = (float)g_hi[j];
    const float lo = (float)g_lo[j];
    const float stability = hi / fmaxf(lo, 1.0f);

    const int minr = g_minr[j], maxr = g_maxr[j];
    const int minc = g_minc[j], maxc = g_maxc[j];
    const bool empty = (maxr < 0);
    const float bl = empty ? 0.0f : (float)minc;
    const float bt = empty ? 0.0f : (float)minr;
    const float br = empty ? 0.0f : (float)maxc;
    const float bb = empty ? 0.0f : (float)maxr;

    const bool valid = (score > IOU_THRESH) && (stability >= 0.95f);

    // ---- stable compaction of valid entries (ballot) ----
    const unsigned ballot = __ballot_sync(0xFFFFFFFFu, valid);
    if ((j & 31) == 0) s_wcnt[wid] = __popc(ballot);
    __syncthreads();

    int warp_off = 0, nvalid = 0;
#pragma unroll
    for (int k = 0; k < 32; ++k) {
        const int c = s_wcnt[k];
        if (k < wid) warp_off += c;
        nvalid += c;
    }
    const int cpos = warp_off + __popc(ballot & lane_lt);

    if (valid) {
        s_ckey[cpos] = score;
        s_cidx[cpos] = j;
    }
    __syncthreads();

    // ---- stable descending rank among valid entries only ----
    int rank = 0;
    if (valid) {
        for (int i = 0; i < nvalid; ++i) {
            const float kk = s_ckey[i];
            rank += (kk > score) || ((kk == score) && (s_cidx[i] < j));
        }
        s_sl[rank] = bl; s_st[rank] = bt; s_sr[rank] = br; s_sb[rank] = bb;
        s_sa[rank] = fmaxf(br - bl, 0.0f) * fmaxf(bb - bt, 0.0f);
    }
    __syncthreads();

    // ---- warp 0: predicated greedy NMS (uniform inner trips) ----
    if (j < 32) {
        const int lane = j;
        const int nslot = (nvalid + 31) >> 5;
        unsigned alive = 0;
        for (int t = 0; t < nslot; ++t)
            if (lane + (t << 5) < nvalid) alive |= (1u << t);

        for (int i = 0; i < nvalid; ++i) {
            const unsigned oa = __shfl_sync(0xFFFFFFFFu, alive, i & 31);
            if ((oa >> (i >> 5)) & 1) {                 // warp-uniform test
                const float il = s_sl[i], it_ = s_st[i];
                const float ir = s_sr[i], ib = s_sb[i];
                const float areaI = s_sa[i];
                for (int t = 0; t < nslot; ++t) {       // uniform trip count
                    const int jj = lane + (t << 5);
                    const bool act = (jj > i) && (jj < nvalid) && ((alive >> t) & 1);
                    const float tl = s_sl[jj], tt = s_st[jj];
                    const float tr = s_sr[jj], tb = s_sb[jj];
                    const float x0 = fmaxf(il, tl), y0 = fmaxf(it_, tt);
                    const float x1 = fminf(ir, tr), y1 = fminf(ib, tb);
                    const float inter = fmaxf(x1 - x0, 0.0f) * fmaxf(y1 - y0, 0.0f);
                    const float uni = fmaxf(areaI + s_sa[jj] - inter, 1e-6f);
                    if (act && (inter / uni > 0.7f)) alive &= ~(1u << t);
                }
            }
        }
        for (int t = 0; t < nslot; ++t) {
            const int jj = lane + (t << 5);
            if (jj < nvalid) s_keep[jj] = (alive >> t) & 1;
        }
    }
    __syncthreads();

    const bool kept = valid && (s_keep[rank] != 0);
    g_gated[j] = kept ? score : 0.0f;

    out[OUT_KEEP_OFF + j] = kept ? 1.0f : 0.0f;
    float* ob = out + OUT_BOX_OFF + (size_t)j * 4;
    ob[0] = bl; ob[1] = bt; ob[2] = br; ob[3] = bb;
}

// ============================================================
// Kernel O — EXACT R4 out kernel (measured 37.5us in R6 config):
// 4096 blocks, early exit for iou-fail, zero or sigmoid*g.
// ============================================================
__global__ void __launch_bounds__(256) sam_out_kernel(const float* __restrict__ logits,
                                                      const float* __restrict__ iou_preds,
                                                      float* __restrict__ out)
{
    const int n = blockIdx.x >> 2;
    if (iou_preds[n] <= IOU_THRESH) return;   // already zeroed in fused kernel
    const int q = blockIdx.x & 3;
    const float g = g_gated[n];

    const size_t base4 = (size_t)n * (HW / 4) + (size_t)q * (HW / 16);
    const float4* __restrict__ in4 = reinterpret_cast<const float4*>(logits) + base4;
    float4* __restrict__ o4 = reinterpret_cast<float4*>(out) + base4;
    const int tid = threadIdx.x;

    if (g == 0.0f) {
        const float4 z = make_float4(0.0f, 0.0f, 0.0f, 0.0f);
#pragma unroll
        for (int it = 0; it < 16; ++it)
            o4[it * 256 + tid] = z;
    } else {
#pragma unroll 4
        for (int it = 0; it < 16; ++it) {
            float4 v = in4[it * 256 + tid];
            v.x = g / (1.0f + __expf(-v.x));
            v.y = g / (1.0f + __expf(-v.y));
            v.z = g / (1.0f + __expf(-v.z));
            v.w = g / (1.0f + __expf(-v.w));
            o4[it * 256 + tid] = v;
        }
    }
}

extern "C" void kernel_launch(void* const* d_in, const int* in_sizes, int n_in,
                              void* d_out, int out_size)
{
    const float* logits    = (const float*)d_in[0];  // [1024,256,256]
    const float* iou_preds = (const float*)d_in[1];  // [1024]
    float* out = (float*)d_out;

    sam_fused_kernel<<<NM + NM * 4, 256>>>(logits, iou_preds, out);
    sam_nms_kernel<<<1, 1024>>>(iou_preds, out);
    sam_out_kernel<<<NM * 4, 256>>>(logits, iou_preds, out);
}